// round 11
// baseline (speedup 1.0000x reference)
#include <cuda_runtime.h>

#define NSEQ 12800
#define TSTEPS 512
#define CHUNK_T 8
#define NCHUNK (TSTEPS / CHUNK_T)

typedef unsigned long long u64;

// ---------- packed f32x2 + fast-math helpers ----------
__device__ __forceinline__ u64 pk2(float lo, float hi) {
    u64 u; asm("mov.b64 %0, {%1,%2};" : "=l"(u) : "f"(lo), "f"(hi)); return u;
}
__device__ __forceinline__ float2 upk2(u64 u) {
    float2 v; asm("mov.b64 {%0,%1}, %2;" : "=f"(v.x), "=f"(v.y) : "l"(u)); return v;
}
__device__ __forceinline__ u64 ffma2(u64 a, u64 b, u64 c) {
    u64 d; asm("fma.rn.f32x2 %0, %1, %2, %3;" : "=l"(d) : "l"(a), "l"(b), "l"(c)); return d;
}
__device__ __forceinline__ float tanh_a(float x) {
    float r; asm("tanh.approx.f32 %0, %1;" : "=f"(r) : "f"(x)); return r;
}
__device__ __forceinline__ float hsum(u64 a) { float2 v = upk2(a); return v.x + v.y; }

// r/z gate weights pre-scaled by 0.5: sigmoid(x) = 0.5*tanh(x/2) + 0.5  (1 MUFU)
#define KRZ (0.5f)

// ---------- global scratch: ping-pong activation buffers, layout (T, N, 16) ----------
__device__ float g_bufA[(size_t)TSTEPS * NSEQ * 16];
__device__ float g_bufB[(size_t)TSTEPS * NSEQ * 16];

// ---------- per-WARP cp.async chunk loader (8 scans per warp) ----------
// warp-private chunk layout: [tt (CHUNK_T)][scan (8)][INF floats + 16B pad]
template <int INF, bool RAW>
__device__ __forceinline__ void issue_chunk_w(char* dst, const float* __restrict__ x_in,
                                              int n0, int c, int dir, int lane) {
    constexpr int VPS = INF / 4;                 // 16B vectors per scan row
    constexpr int ROW_B = INF * 4 + 16;
    constexpr int TT_B = 8 * ROW_B;
    constexpr int PER_TT = 8 * VPS;              // lanes covering one tt
    constexpr int TT_PER_K = 32 / PER_TT;        // tt advance per iteration
    const int tt0  = lane / PER_TT;
    const int scan = (lane % PER_TT) / VPS;
    const int c16  = lane % VPS;
    const int t00 = dir ? (TSTEPS - 1 - c * CHUNK_T - tt0) : (c * CHUNK_T + tt0);
    const float* g = RAW
        ? x_in + (size_t)(n0 + scan) * 4096 + (size_t)t00 * 8 + c16 * 4
        : x_in + ((size_t)t00 * NSEQ + (size_t)(n0 + scan)) * 16 + c16 * 4;
    const ptrdiff_t gstep = (RAW ? (ptrdiff_t)8 : (ptrdiff_t)NSEQ * 16)
                          * (dir ? -TT_PER_K : TT_PER_K);
    unsigned s = (unsigned)__cvta_generic_to_shared(dst + tt0 * TT_B + scan * ROW_B + c16 * 16);
#pragma unroll
    for (int k = 0; k < CHUNK_T / TT_PER_K; k++) {
        asm volatile("cp.async.cg.shared.global [%0], [%1], 16;" :: "r"(s), "l"(g));
        s += TT_PER_K * TT_B;
        g += gstep;
    }
}

// One bidirectional-GRU layer. Each WARP owns 8 scans of one direction as TWO
// independent recurrence chains (lane u of group sg handles unit u of scans
// n0+sg and n0+4+sg). Weight registers are shared across both chains; the
// chains' dependency graphs interleave, covering shfl/tanh latency with ILP.
// Private double-buffered cp.async x-ring per warp, no __syncthreads.
// Issue order per step: all 16 shfls -> 48 independent x-proj FFMAs (covers
// shfl latency under in-order issue) -> h-recurrence -> interleaved gates.
// HEAD (layer 3): fwd only, no stores; fused 1-step bwd GRU at t=T-1 (h0=0)
// + lin1/LeakyReLU(0.2)/lin2 head for both chains.
template <int INF, bool RAW_IN, bool HEAD, int MINB>
__global__ void __launch_bounds__(128, MINB)
gru_layer_kernel(const float* __restrict__ x_in, float* __restrict__ x_out,
                 const float* __restrict__ Wih, const float* __restrict__ Whh,
                 const float* __restrict__ bih, const float* __restrict__ bhh,
                 int wih_stride,
                 const float* __restrict__ l1w, const float* __restrict__ l1b,
                 const float* __restrict__ l2w, const float* __restrict__ l2b,
                 float* __restrict__ out)
{
    constexpr int IN_PAIRS = INF / 2;
    constexpr int ROW_B = INF * 4 + 16;
    constexpr int TT_B = 8 * ROW_B;
    constexpr int CHUNK_B = CHUNK_T * TT_B;
    constexpr int WARP_B = 2 * CHUNK_B;

    extern __shared__ char sb[];

    const int tid = threadIdx.x;
    const int wid = tid >> 5;
    const int lane = tid & 31;
    const int u = tid & 7;
    const int sg = (tid >> 3) & 3;               // scan group within warp
    const int warpG = blockIdx.x * 4 + wid;
    const int dir = HEAD ? 0 : (warpG / (NSEQ / 8));
    const int wi  = HEAD ? warpG : (warpG % (NSEQ / 8));
    const int n0 = wi * 8;
    const int nA = n0 + sg;
    const int nB = n0 + 4 + sg;
    char* wsb = sb + wid * WARP_B;               // this warp's private ring

    // ---- register weights, pre-scaled (SHARED by both chains) ----
    const float* wih = Wih + dir * wih_stride;
    const float* whh = Whh + dir * 192;
    const float* bi  = bih + dir * 24;
    const float* bh  = bhh + dir * 24;

    u64 wr[IN_PAIRS], wz[IN_PAIRS], wn[IN_PAIRS];
#pragma unroll
    for (int p = 0; p < IN_PAIRS; p++) {
        wr[p] = pk2(KRZ * wih[(u     ) * INF + 2 * p], KRZ * wih[(u     ) * INF + 2 * p + 1]);
        wz[p] = pk2(KRZ * wih[(u +  8) * INF + 2 * p], KRZ * wih[(u +  8) * INF + 2 * p + 1]);
        wn[p] = pk2(       wih[(u + 16) * INF + 2 * p],        wih[(u + 16) * INF + 2 * p + 1]);
    }
    u64 ur[4], uz[4], un[4];
#pragma unroll
    for (int p = 0; p < 4; p++) {
        ur[p] = pk2(KRZ * whh[(u     ) * 8 + 2 * p], KRZ * whh[(u     ) * 8 + 2 * p + 1]);
        uz[p] = pk2(KRZ * whh[(u +  8) * 8 + 2 * p], KRZ * whh[(u +  8) * 8 + 2 * p + 1]);
        un[p] = pk2(       whh[(u + 16) * 8 + 2 * p],        whh[(u + 16) * 8 + 2 * p + 1]);
    }
    const u64 brp  = pk2(KRZ * (bi[u]     + bh[u]),     0.0f);
    const u64 bzp  = pk2(KRZ * (bi[u + 8] + bh[u + 8]), 0.0f);
    const u64 bnxp = pk2(bi[u + 16], 0.0f);
    const u64 bnhp = pk2(bh[u + 16], 0.0f);

    const int t0 = dir ? (TSTEPS - 1) : 0;
    float* opA = HEAD ? nullptr
                      : (x_out + ((size_t)t0 * NSEQ + (size_t)nA) * 16 + dir * 8 + u);
    float* opB = HEAD ? nullptr
                      : (x_out + ((size_t)t0 * NSEQ + (size_t)nB) * 16 + dir * 8 + u);
    const ptrdiff_t ostep = (ptrdiff_t)NSEQ * 16 * (dir ? -1 : 1);

    // ---- prime the per-warp pipeline ----
    issue_chunk_w<INF, RAW_IN>(wsb, x_in, n0, 0, dir, lane);
    asm volatile("cp.async.commit_group;" ::: "memory");
    issue_chunk_w<INF, RAW_IN>(wsb + CHUNK_B, x_in, n0, 1, dir, lane);
    asm volatile("cp.async.commit_group;" ::: "memory");

    float hA = 0.0f, hB = 0.0f;

#pragma unroll 1
    for (int c = 0; c < NCHUNK; c++) {
        asm volatile("cp.async.wait_group 1;" ::: "memory");
        __syncwarp();
        const char* xbA = wsb + (c & 1) * CHUNK_B + sg * ROW_B;
        const char* xbB = xbA + 4 * ROW_B;

#pragma unroll
        for (int tt = 0; tt < CHUNK_T; tt++) {
            // ---- all 16 shfls up front (independent; pipeline in MIO) ----
            u64 hpA[4], hpB[4];
#pragma unroll
            for (int p = 0; p < 4; p++) {
                float loA = __shfl_sync(0xffffffffu, hA, 2 * p,     8);
                float hiA = __shfl_sync(0xffffffffu, hA, 2 * p + 1, 8);
                float loB = __shfl_sync(0xffffffffu, hB, 2 * p,     8);
                float hiB = __shfl_sync(0xffffffffu, hB, 2 * p + 1, 8);
                hpA[p] = pk2(loA, hiA);
                hpB[p] = pk2(loB, hiB);
            }

            // ---- x-projections (independent of h; cover shfl latency) ----
            const ulonglong2* qA = reinterpret_cast<const ulonglong2*>(xbA + tt * TT_B);
            const ulonglong2* qB = reinterpret_cast<const ulonglong2*>(xbB + tt * TT_B);
            u64 arA = brp, azA = bzp, axnA = bnxp;
            u64 arB = brp, azB = bzp, axnB = bnxp;
#pragma unroll
            for (int blk = 0; blk < IN_PAIRS / 4; blk++) {
                ulonglong2 va = qA[2 * blk];
                ulonglong2 vb = qA[2 * blk + 1];
                arA  = ffma2(wr[4 * blk + 0], va.x, arA);
                azA  = ffma2(wz[4 * blk + 0], va.x, azA);
                axnA = ffma2(wn[4 * blk + 0], va.x, axnA);
                arA  = ffma2(wr[4 * blk + 1], va.y, arA);
                azA  = ffma2(wz[4 * blk + 1], va.y, azA);
                axnA = ffma2(wn[4 * blk + 1], va.y, axnA);
                arA  = ffma2(wr[4 * blk + 2], vb.x, arA);
                azA  = ffma2(wz[4 * blk + 2], vb.x, azA);
                axnA = ffma2(wn[4 * blk + 2], vb.x, axnA);
                arA  = ffma2(wr[4 * blk + 3], vb.y, arA);
                azA  = ffma2(wz[4 * blk + 3], vb.y, azA);
                axnA = ffma2(wn[4 * blk + 3], vb.y, axnA);
                ulonglong2 wa = qB[2 * blk];
                ulonglong2 wb = qB[2 * blk + 1];
                arB  = ffma2(wr[4 * blk + 0], wa.x, arB);
                azB  = ffma2(wz[4 * blk + 0], wa.x, azB);
                axnB = ffma2(wn[4 * blk + 0], wa.x, axnB);
                arB  = ffma2(wr[4 * blk + 1], wa.y, arB);
                azB  = ffma2(wz[4 * blk + 1], wa.y, azB);
                axnB = ffma2(wn[4 * blk + 1], wa.y, axnB);
                arB  = ffma2(wr[4 * blk + 2], wb.x, arB);
                azB  = ffma2(wz[4 * blk + 2], wb.x, azB);
                axnB = ffma2(wn[4 * blk + 2], wb.x, axnB);
                arB  = ffma2(wr[4 * blk + 3], wb.y, arB);
                azB  = ffma2(wz[4 * blk + 3], wb.y, azB);
                axnB = ffma2(wn[4 * blk + 3], wb.y, axnB);
            }

            // ---- h-recurrence (shfl results long since arrived) ----
            u64 ahnA = bnhp, ahnB = bnhp;
#pragma unroll
            for (int p = 0; p < 4; p++) {
                arA  = ffma2(ur[p], hpA[p], arA);
                azA  = ffma2(uz[p], hpA[p], azA);
                ahnA = ffma2(un[p], hpA[p], ahnA);
                arB  = ffma2(ur[p], hpB[p], arB);
                azB  = ffma2(uz[p], hpB[p], azB);
                ahnB = ffma2(un[p], hpB[p], ahnB);
            }

            // ---- gates: interleave the two MUFU chains ----
            float rA = fmaf(0.5f, tanh_a(hsum(arA)), 0.5f);
            float rB = fmaf(0.5f, tanh_a(hsum(arB)), 0.5f);
            float zA = fmaf(0.5f, tanh_a(hsum(azA)), 0.5f);
            float zB = fmaf(0.5f, tanh_a(hsum(azB)), 0.5f);
            float nnA = tanh_a(fmaf(rA, hsum(ahnA), hsum(axnA)));
            float nnB = tanh_a(fmaf(rB, hsum(ahnB), hsum(axnB)));
            hA = fmaf(zA, hA - nnA, nnA);
            hB = fmaf(zB, hB - nnB, nnB);

            if (!HEAD) {
                *opA = hA; opA += ostep;
                *opB = hB; opB += ostep;
            }
        }
        if (c + 2 < NCHUNK)
            issue_chunk_w<INF, RAW_IN>(wsb + (c & 1) * CHUNK_B, x_in, n0, c + 2, dir, lane);
        asm volatile("cp.async.commit_group;" ::: "memory");
    }

    if (HEAD) {
        // x[T-1] for both chains still resident in the last chunk's buffer
        const char* xlast = wsb + ((NCHUNK - 1) & 1) * CHUNK_B + (CHUNK_T - 1) * TT_B;
        const u64* qA = reinterpret_cast<const u64*>(xlast + sg * ROW_B);
        const u64* qB = reinterpret_cast<const u64*>(xlast + (4 + sg) * ROW_B);

        // backward-direction single step at t=T-1, h0=0 (gh = b_hh)
        const float* wihB = Wih + wih_stride;
        const float* biB  = bih + 24;
        const float* bhB  = bhh + 24;
        u64 arA = pk2(KRZ * (biB[u]     + bhB[u]),     0.0f), arB = arA;
        u64 azA = pk2(KRZ * (biB[u + 8] + bhB[u + 8]), 0.0f), azB = azA;
        u64 axA = pk2(biB[u + 16], 0.0f),                     axB = axA;
        const float bnh2 = bhB[u + 16];
#pragma unroll
        for (int p = 0; p < IN_PAIRS; p++) {
            u64 wr2 = pk2(KRZ * wihB[(u     ) * INF + 2 * p], KRZ * wihB[(u     ) * INF + 2 * p + 1]);
            u64 wz2 = pk2(KRZ * wihB[(u +  8) * INF + 2 * p], KRZ * wihB[(u +  8) * INF + 2 * p + 1]);
            u64 wn2 = pk2(       wihB[(u + 16) * INF + 2 * p],        wihB[(u + 16) * INF + 2 * p + 1]);
            arA = ffma2(wr2, qA[p], arA);  arB = ffma2(wr2, qB[p], arB);
            azA = ffma2(wz2, qA[p], azA);  azB = ffma2(wz2, qB[p], azB);
            axA = ffma2(wn2, qA[p], axA);  axB = ffma2(wn2, qB[p], axB);
        }
        float rA = fmaf(0.5f, tanh_a(hsum(arA)), 0.5f);
        float rB = fmaf(0.5f, tanh_a(hsum(arB)), 0.5f);
        float zA = fmaf(0.5f, tanh_a(hsum(azA)), 0.5f);
        float zB = fmaf(0.5f, tanh_a(hsum(azB)), 0.5f);
        float nnA = tanh_a(fmaf(rA, bnh2, hsum(axA)));
        float nnB = tanh_a(fmaf(rB, bnh2, hsum(axB)));
        float hbA = (1.0f - zA) * nnA;   // h0 = 0
        float hbB = (1.0f - zB) * nnB;

        // head for both chains: lin1 + LeakyReLU(0.2) + lin2 over [h_f ; h_b]
        float midA = l1b[u], midB = midA;
#pragma unroll
        for (int cc = 0; cc < 8; cc++) {
            float hfA = __shfl_sync(0xffffffffu, hA,  cc, 8);
            float hbA_ = __shfl_sync(0xffffffffu, hbA, cc, 8);
            float hfB = __shfl_sync(0xffffffffu, hB,  cc, 8);
            float hbB_ = __shfl_sync(0xffffffffu, hbB, cc, 8);
            float w1 = l1w[u * 16 + cc], w2 = l1w[u * 16 + 8 + cc];
            midA = fmaf(w1, hfA, midA);  midA = fmaf(w2, hbA_, midA);
            midB = fmaf(w1, hfB, midB);  midB = fmaf(w2, hbB_, midB);
        }
        float actA = (midA >= 0.0f) ? midA : 0.2f * midA;
        float actB = (midB >= 0.0f) ? midB : 0.2f * midB;

        float oA = l2b[u], oB = oA;
#pragma unroll
        for (int cc = 0; cc < 8; cc++) {
            float aA = __shfl_sync(0xffffffffu, actA, cc, 8);
            float aB = __shfl_sync(0xffffffffu, actB, cc, 8);
            float w = l2w[u * 8 + cc];
            oA = fmaf(w, aA, oA);
            oB = fmaf(w, aB, oB);
        }
        out[(size_t)nA * 8 + u] = oA;
        out[(size_t)nB * 8 + u] = oB;
    }
}

extern "C" void kernel_launch(void* const* d_in, const int* in_sizes, int n_in,
                              void* d_out, int out_size) {
    (void)in_sizes; (void)n_in; (void)out_size;
    const float* raw  = (const float*)d_in[0];
    const float* Wih0 = (const float*)d_in[1];
    const float* Whh0 = (const float*)d_in[2];
    const float* bih0 = (const float*)d_in[3];
    const float* bhh0 = (const float*)d_in[4];
    const float* WihR = (const float*)d_in[5];   // (3, 2, 24, 16)
    const float* WhhR = (const float*)d_in[6];   // (3, 2, 24, 8)
    const float* bihR = (const float*)d_in[7];   // (3, 2, 24)
    const float* bhhR = (const float*)d_in[8];   // (3, 2, 24)
    const float* l1w  = (const float*)d_in[9];
    const float* l1b  = (const float*)d_in[10];
    const float* l2w  = (const float*)d_in[11];
    const float* l2b  = (const float*)d_in[12];
    float* out = (float*)d_out;

    float *bufA, *bufB;
    cudaGetSymbolAddress((void**)&bufA, g_bufA);
    cudaGetSymbolAddress((void**)&bufB, g_bufB);

    const int BLK_FULL = 2 * (NSEQ / 32);   // 800 blocks (fwd + bwd, 8 scans/warp)
    const int BLK_HEAD = NSEQ / 32;         // 400 blocks (fwd only)
    const int SMEM8  = 4 * 2 * CHUNK_T * 8 * (8 * 4 + 16);    // 24576
    const int SMEM16 = 4 * 2 * CHUNK_T * 8 * (16 * 4 + 16);   // 40960

    // Layer 0: raw -> bufA  (half-size weight set)
    gru_layer_kernel<8, true, false, 4><<<BLK_FULL, 128, SMEM8>>>(
        raw, bufA, Wih0, Whh0, bih0, bhh0, 192,
        nullptr, nullptr, nullptr, nullptr, nullptr);

    // Layer 1: bufA -> bufB
    gru_layer_kernel<16, false, false, 3><<<BLK_FULL, 128, SMEM16>>>(
        bufA, bufB, WihR + 0 * 768, WhhR + 0 * 384, bihR + 0 * 48, bhhR + 0 * 48, 384,
        nullptr, nullptr, nullptr, nullptr, nullptr);

    // Layer 2: bufB -> bufA
    gru_layer_kernel<16, false, false, 3><<<BLK_FULL, 128, SMEM16>>>(
        bufB, bufA, WihR + 1 * 768, WhhR + 1 * 384, bihR + 1 * 48, bhhR + 1 * 48, 384,
        nullptr, nullptr, nullptr, nullptr, nullptr);

    // Layer 3 + head: bufA -> out
    gru_layer_kernel<16, false, true, 3><<<BLK_HEAD, 128, SMEM16>>>(
        bufA, nullptr, WihR + 2 * 768, WhhR + 2 * 384, bihR + 2 * 48, bhhR + 2 * 48, 384,
        l1w, l1b, l2w, l2b, out);
}

// round 12
// speedup vs baseline: 1.1163x; 1.1163x over previous
#include <cuda_runtime.h>

#define NSEQ 12800
#define TSTEPS 512
#define CHUNK_T 8
#define NCHUNK (TSTEPS / CHUNK_T)
#define RING 4

typedef unsigned long long u64;

// ---------- packed f32x2 + fast-math helpers ----------
__device__ __forceinline__ u64 pk2(float lo, float hi) {
    u64 u; asm("mov.b64 %0, {%1,%2};" : "=l"(u) : "f"(lo), "f"(hi)); return u;
}
__device__ __forceinline__ float2 upk2(u64 u) {
    float2 v; asm("mov.b64 {%0,%1}, %2;" : "=f"(v.x), "=f"(v.y) : "l"(u)); return v;
}
__device__ __forceinline__ u64 ffma2(u64 a, u64 b, u64 c) {
    u64 d; asm("fma.rn.f32x2 %0, %1, %2, %3;" : "=l"(d) : "l"(a), "l"(b), "l"(c)); return d;
}
__device__ __forceinline__ float tanh_a(float x) {
    float r; asm("tanh.approx.f32 %0, %1;" : "=f"(r) : "f"(x)); return r;
}
__device__ __forceinline__ float hsum(u64 a) { float2 v = upk2(a); return v.x + v.y; }

// r/z gate weights pre-scaled by 0.5: sigmoid(x) = 0.5*tanh(x/2) + 0.5  (1 MUFU)
#define KRZ (0.5f)

// ---------- global scratch: ping-pong activation buffers, layout (T, N, 16) ----------
__device__ float g_bufA[(size_t)TSTEPS * NSEQ * 16];
__device__ float g_bufB[(size_t)TSTEPS * NSEQ * 16];

// ---------- per-WARP cp.async chunk loader (no block barriers anywhere) ----------
// warp-private chunk layout: [tt (CHUNK_T)][scan (4)][INF floats + 16B pad]
template <int INF, bool RAW>
__device__ __forceinline__ void issue_chunk_w(char* dst, const float* __restrict__ x_in,
                                              int n0, int c, int dir, int lane) {
    constexpr int VPS = INF / 4;                 // 16B vectors per scan row
    constexpr int ROW_B = INF * 4 + 16;
    constexpr int TT_B = 4 * ROW_B;
    constexpr int PER_TT = 4 * VPS;              // lanes covering one tt
    constexpr int TT_PER_K = 32 / PER_TT;        // tt advance per iteration
    const int tt0  = lane / PER_TT;
    const int scan = (lane % PER_TT) / VPS;
    const int c16  = lane % VPS;
    const int t00 = dir ? (TSTEPS - 1 - c * CHUNK_T - tt0) : (c * CHUNK_T + tt0);
    const float* g = RAW
        ? x_in + (size_t)(n0 + scan) * 4096 + (size_t)t00 * 8 + c16 * 4
        : x_in + ((size_t)t00 * NSEQ + (size_t)(n0 + scan)) * 16 + c16 * 4;
    const ptrdiff_t gstep = (RAW ? (ptrdiff_t)8 : (ptrdiff_t)NSEQ * 16)
                          * (dir ? -TT_PER_K : TT_PER_K);
    unsigned s = (unsigned)__cvta_generic_to_shared(dst + tt0 * TT_B + scan * ROW_B + c16 * 16);
#pragma unroll
    for (int k = 0; k < CHUNK_T / TT_PER_K; k++) {
        asm volatile("cp.async.cg.shared.global [%0], [%1], 16;" :: "r"(s), "l"(g));
        s += TT_PER_K * TT_B;
        g += gstep;
    }
}

// One bidirectional-GRU layer. Each WARP owns 4 scans of one direction and
// free-runs on a private 4-deep cp.async x-ring (prefetch distance 3 chunks
// ~= 3300 cyc, covering loaded-chip DRAM latency). No __syncthreads.
// 8 lanes per scan; lane u owns hidden unit u (gate rows u, u+8, u+16).
// SOFTWARE PIPELINE: step t+1's x-projection (independent of h_t) is
// accumulated during step t's shfl/tanh dependency chain. Weights in regs.
// HEAD (layer 3): fwd only, no stores; fused 1-step bwd GRU at t=T-1 (h0=0)
// + lin1/LeakyReLU(0.2)/lin2 head.
template <int INF, bool RAW_IN, bool HEAD, int MINB>
__global__ void __launch_bounds__(128, MINB)
gru_layer_kernel(const float* __restrict__ x_in, float* __restrict__ x_out,
                 const float* __restrict__ Wih, const float* __restrict__ Whh,
                 const float* __restrict__ bih, const float* __restrict__ bhh,
                 int wih_stride,
                 const float* __restrict__ l1w, const float* __restrict__ l1b,
                 const float* __restrict__ l2w, const float* __restrict__ l2b,
                 float* __restrict__ out)
{
    constexpr int IN_PAIRS = INF / 2;
    constexpr int ROW_B = INF * 4 + 16;
    constexpr int TT_B = 4 * ROW_B;
    constexpr int CHUNK_B = CHUNK_T * TT_B;
    constexpr int WARP_B = RING * CHUNK_B;

    extern __shared__ char sb[];

    const int tid = threadIdx.x;
    const int wid = tid >> 5;
    const int lane = tid & 31;
    const int u = tid & 7;
    const int sg = (tid >> 3) & 3;               // scan within warp
    const int warpG = blockIdx.x * 4 + wid;
    const int dir = HEAD ? 0 : (warpG / (NSEQ / 4));
    const int wi  = HEAD ? warpG : (warpG % (NSEQ / 4));
    const int n0 = wi * 4;
    const int n = n0 + sg;
    char* wsb = sb + wid * WARP_B;               // this warp's private ring

    // ---- register weights, pre-scaled ----
    const float* wih = Wih + dir * wih_stride;
    const float* whh = Whh + dir * 192;
    const float* bi  = bih + dir * 24;
    const float* bh  = bhh + dir * 24;

    u64 wr[IN_PAIRS], wz[IN_PAIRS], wn[IN_PAIRS];
#pragma unroll
    for (int p = 0; p < IN_PAIRS; p++) {
        wr[p] = pk2(KRZ * wih[(u     ) * INF + 2 * p], KRZ * wih[(u     ) * INF + 2 * p + 1]);
        wz[p] = pk2(KRZ * wih[(u +  8) * INF + 2 * p], KRZ * wih[(u +  8) * INF + 2 * p + 1]);
        wn[p] = pk2(       wih[(u + 16) * INF + 2 * p],        wih[(u + 16) * INF + 2 * p + 1]);
    }
    u64 ur[4], uz[4], un[4];
#pragma unroll
    for (int p = 0; p < 4; p++) {
        ur[p] = pk2(KRZ * whh[(u     ) * 8 + 2 * p], KRZ * whh[(u     ) * 8 + 2 * p + 1]);
        uz[p] = pk2(KRZ * whh[(u +  8) * 8 + 2 * p], KRZ * whh[(u +  8) * 8 + 2 * p + 1]);
        un[p] = pk2(       whh[(u + 16) * 8 + 2 * p],        whh[(u + 16) * 8 + 2 * p + 1]);
    }
    const u64 brp  = pk2(KRZ * (bi[u]     + bh[u]),     0.0f);
    const u64 bzp  = pk2(KRZ * (bi[u + 8] + bh[u + 8]), 0.0f);
    const u64 bnxp = pk2(bi[u + 16], 0.0f);
    const u64 bnhp = pk2(bh[u + 16], 0.0f);

    const int t0 = dir ? (TSTEPS - 1) : 0;
    float* op = HEAD ? nullptr
                     : (x_out + ((size_t)t0 * NSEQ + (size_t)n) * 16 + dir * 8 + u);
    const ptrdiff_t ostep = (ptrdiff_t)NSEQ * 16 * (dir ? -1 : 1);

    // pipelined x-projection accumulators (carry bias + x·W for the NEXT step)
    u64 ar, az, axn;
    auto accum_x = [&](const char* qp) {
        const ulonglong2* q = reinterpret_cast<const ulonglong2*>(qp);
        ar = brp; az = bzp; axn = bnxp;
#pragma unroll
        for (int blk = 0; blk < IN_PAIRS / 4; blk++) {
            ulonglong2 va = q[2 * blk];
            ulonglong2 vb = q[2 * blk + 1];
            ar  = ffma2(wr[4 * blk + 0], va.x, ar);
            az  = ffma2(wz[4 * blk + 0], va.x, az);
            axn = ffma2(wn[4 * blk + 0], va.x, axn);
            ar  = ffma2(wr[4 * blk + 1], va.y, ar);
            az  = ffma2(wz[4 * blk + 1], va.y, az);
            axn = ffma2(wn[4 * blk + 1], va.y, axn);
            ar  = ffma2(wr[4 * blk + 2], vb.x, ar);
            az  = ffma2(wz[4 * blk + 2], vb.x, az);
            axn = ffma2(wn[4 * blk + 2], vb.x, axn);
            ar  = ffma2(wr[4 * blk + 3], vb.y, ar);
            az  = ffma2(wz[4 * blk + 3], vb.y, az);
            axn = ffma2(wn[4 * blk + 3], vb.y, axn);
        }
    };

    // ---- prime: three chunks in flight, then preaccumulate step 0 ----
    issue_chunk_w<INF, RAW_IN>(wsb, x_in, n0, 0, dir, lane);
    asm volatile("cp.async.commit_group;" ::: "memory");
    issue_chunk_w<INF, RAW_IN>(wsb + CHUNK_B, x_in, n0, 1, dir, lane);
    asm volatile("cp.async.commit_group;" ::: "memory");
    issue_chunk_w<INF, RAW_IN>(wsb + 2 * CHUNK_B, x_in, n0, 2, dir, lane);
    asm volatile("cp.async.commit_group;" ::: "memory");
    asm volatile("cp.async.wait_group 2;" ::: "memory");
    __syncwarp();

    float h = 0.0f;
    accum_x(wsb + sg * ROW_B);     // chunk 0, tt 0

#pragma unroll 1
    for (int c = 0; c < NCHUNK; c++) {
        const char* xbase = wsb + (c & (RING - 1)) * CHUNK_B + sg * ROW_B;

#pragma unroll
        for (int tt = 0; tt < CHUNK_T; tt++) {
            // h broadcast, consumed pair-by-pair (keeps 1 hp pair live)
            u64 ahn = bnhp;
#pragma unroll
            for (int p = 0; p < 4; p++) {
                float lo = __shfl_sync(0xffffffffu, h, 2 * p,     8);
                float hi = __shfl_sync(0xffffffffu, h, 2 * p + 1, 8);
                u64 hp = pk2(lo, hi);
                ar  = ffma2(ur[p], hp, ar);
                az  = ffma2(uz[p], hp, az);
                ahn = ffma2(un[p], hp, ahn);
            }
            // snapshot gate sums, then recycle accumulators for step t+1's x
            float sr = hsum(ar), sz = hsum(az);
            float sxn = hsum(axn), shn = hsum(ahn);
            if (tt < CHUNK_T - 1)
                accum_x(xbase + (tt + 1) * TT_B);   // overlaps the tanh chain

            float r = fmaf(0.5f, tanh_a(sr), 0.5f);   // sigmoid
            float z = fmaf(0.5f, tanh_a(sz), 0.5f);   // sigmoid
            float nn = tanh_a(fmaf(r, shn, sxn));
            h = fmaf(z, h - nn, nn);

            if (!HEAD) { *op = h; op += ostep; }
        }
        // refill ring slot 3 ahead, then wait for the next chunk and
        // preaccumulate its first step
        if (c + 3 < NCHUNK)
            issue_chunk_w<INF, RAW_IN>(wsb + ((c + 3) & (RING - 1)) * CHUNK_B,
                                       x_in, n0, c + 3, dir, lane);
        asm volatile("cp.async.commit_group;" ::: "memory");
        if (c + 1 < NCHUNK) {
            asm volatile("cp.async.wait_group 2;" ::: "memory");
            __syncwarp();
            accum_x(wsb + ((c + 1) & (RING - 1)) * CHUNK_B + sg * ROW_B);
        }
    }

    if (HEAD) {
        // x[T-1] still resident in the last chunk's ring slot
        const char* xrow = wsb + ((NCHUNK - 1) & (RING - 1)) * CHUNK_B
                         + sg * ROW_B + (CHUNK_T - 1) * TT_B;
        const u64* q = reinterpret_cast<const u64*>(xrow);

        // backward-direction single step at t=T-1, h0=0 (gh = b_hh)
        const float* wihB = Wih + wih_stride;
        const float* biB  = bih + 24;
        const float* bhB  = bhh + 24;
        u64 br2 = pk2(KRZ * (biB[u]     + bhB[u]),     0.0f);
        u64 bz2 = pk2(KRZ * (biB[u + 8] + bhB[u + 8]), 0.0f);
        u64 bx2 = pk2(biB[u + 16], 0.0f);
        const float bnhB = bhB[u + 16];
#pragma unroll
        for (int p = 0; p < IN_PAIRS; p++) {
            u64 xcp = q[p];
            u64 wrB = pk2(KRZ * wihB[(u     ) * INF + 2 * p], KRZ * wihB[(u     ) * INF + 2 * p + 1]);
            u64 wzB = pk2(KRZ * wihB[(u +  8) * INF + 2 * p], KRZ * wihB[(u +  8) * INF + 2 * p + 1]);
            u64 wnB = pk2(       wihB[(u + 16) * INF + 2 * p],        wihB[(u + 16) * INF + 2 * p + 1]);
            br2 = ffma2(wrB, xcp, br2);
            bz2 = ffma2(wzB, xcp, bz2);
            bx2 = ffma2(wnB, xcp, bx2);
        }
        float r = fmaf(0.5f, tanh_a(hsum(br2)), 0.5f);
        float z = fmaf(0.5f, tanh_a(hsum(bz2)), 0.5f);
        float nn = tanh_a(fmaf(r, bnhB, hsum(bx2)));
        float hb = (1.0f - z) * nn;   // h0 = 0

        // head: lin1 + LeakyReLU(0.2) + lin2 over [h_f ; h_b]
        float mid = l1b[u];
#pragma unroll
        for (int cc = 0; cc < 8; cc++) {
            float hf_c = __shfl_sync(0xffffffffu, h,  cc, 8);
            float hb_c = __shfl_sync(0xffffffffu, hb, cc, 8);
            mid = fmaf(l1w[u * 16 + cc],     hf_c, mid);
            mid = fmaf(l1w[u * 16 + 8 + cc], hb_c, mid);
        }
        float act = (mid >= 0.0f) ? mid : 0.2f * mid;

        float o = l2b[u];
#pragma unroll
        for (int cc = 0; cc < 8; cc++) {
            float a_c = __shfl_sync(0xffffffffu, act, cc, 8);
            o = fmaf(l2w[u * 8 + cc], a_c, o);
        }
        out[(size_t)n * 8 + u] = o;
    }
}

extern "C" void kernel_launch(void* const* d_in, const int* in_sizes, int n_in,
                              void* d_out, int out_size) {
    (void)in_sizes; (void)n_in; (void)out_size;
    const float* raw  = (const float*)d_in[0];
    const float* Wih0 = (const float*)d_in[1];
    const float* Whh0 = (const float*)d_in[2];
    const float* bih0 = (const float*)d_in[3];
    const float* bhh0 = (const float*)d_in[4];
    const float* WihR = (const float*)d_in[5];   // (3, 2, 24, 16)
    const float* WhhR = (const float*)d_in[6];   // (3, 2, 24, 8)
    const float* bihR = (const float*)d_in[7];   // (3, 2, 24)
    const float* bhhR = (const float*)d_in[8];   // (3, 2, 24)
    const float* l1w  = (const float*)d_in[9];
    const float* l1b  = (const float*)d_in[10];
    const float* l2w  = (const float*)d_in[11];
    const float* l2b  = (const float*)d_in[12];
    float* out = (float*)d_out;

    float *bufA, *bufB;
    cudaGetSymbolAddress((void**)&bufA, g_bufA);
    cudaGetSymbolAddress((void**)&bufB, g_bufB);

    const int BLK_FULL = 2 * (NSEQ / 16);   // 1600 blocks (fwd + bwd)
    const int BLK_HEAD = NSEQ / 16;         // 800 blocks (fwd only)
    const int SMEM8  = 4 * RING * CHUNK_T * 4 * (8 * 4 + 16);    // 24576
    const int SMEM16 = 4 * RING * CHUNK_T * 4 * (16 * 4 + 16);   // 40960

    // Layer 0: raw -> bufA  (half-size weight set: 5 blocks/SM, no spills)
    gru_layer_kernel<8, true, false, 5><<<BLK_FULL, 128, SMEM8>>>(
        raw, bufA, Wih0, Whh0, bih0, bhh0, 192,
        nullptr, nullptr, nullptr, nullptr, nullptr);

    // Layer 1: bufA -> bufB
    gru_layer_kernel<16, false, false, 4><<<BLK_FULL, 128, SMEM16>>>(
        bufA, bufB, WihR + 0 * 768, WhhR + 0 * 384, bihR + 0 * 48, bhhR + 0 * 48, 384,
        nullptr, nullptr, nullptr, nullptr, nullptr);

    // Layer 2: bufB -> bufA
    gru_layer_kernel<16, false, false, 4><<<BLK_FULL, 128, SMEM16>>>(
        bufB, bufA, WihR + 1 * 768, WhhR + 1 * 384, bihR + 1 * 48, bhhR + 1 * 48, 384,
        nullptr, nullptr, nullptr, nullptr, nullptr);

    // Layer 3 + head: bufA -> out
    gru_layer_kernel<16, false, true, 4><<<BLK_HEAD, 128, SMEM16>>>(
        bufA, nullptr, WihR + 2 * 768, WhhR + 2 * 384, bihR + 2 * 48, bhhR + 2 * 48, 384,
        l1w, l1b, l2w, l2b, out);
}

// round 14
// speedup vs baseline: 1.3608x; 1.2189x over previous
#include <cuda_runtime.h>
#include <cuda_fp16.h>

#define NSEQ 12800
#define TSTEPS 512
#define CHUNK_T 4
#define NCHUNK (TSTEPS / CHUNK_T)
#define RING 4
#define ROWB 48                      // padded fp16 x-tile row (bytes, 16-aligned, bank-distinct)
#define TILE_B (16 * ROWB)           // 768 B per 16x(K) fp16 tile
#define GRS 26                       // gate smem row stride (words; even rows distinct banks)
#define G_B (16 * GRS * 4)           // 1664 B gate buffer
#define WARP_SMEM (RING * TILE_B + G_B)   // 4736 B per warp

typedef unsigned long long u64;

// ---------- packed f32x2 + fast-math helpers ----------
__device__ __forceinline__ u64 pk2(float lo, float hi) {
    u64 u; asm("mov.b64 %0, {%1,%2};" : "=l"(u) : "f"(lo), "f"(hi)); return u;
}
__device__ __forceinline__ float2 upk2(u64 u) {
    float2 v; asm("mov.b64 {%0,%1}, %2;" : "=f"(v.x), "=f"(v.y) : "l"(u)); return v;
}
__device__ __forceinline__ u64 ffma2(u64 a, u64 b, u64 c) {
    u64 d; asm("fma.rn.f32x2 %0, %1, %2, %3;" : "=l"(d) : "l"(a), "l"(b), "l"(c)); return d;
}
__device__ __forceinline__ float tanh_a(float x) {
    float r; asm("tanh.approx.f32 %0, %1;" : "=f"(r) : "f"(x)); return r;
}
__device__ __forceinline__ float hsum(u64 a) { float2 v = upk2(a); return v.x + v.y; }

// sigmoid(y) = 0.5*tanh(0.5*y) + 0.5 ; the 0.5 factor is pre-folded into the
// r/z weights and biases (both x-side, via MMA B/C fragments, and h-side).
#define KRZ (0.5f)

// ---------- global scratch ----------
// fp16 inter-layer activations, layout (T, N, 16); fp16 raw copy (N, T, 8).
__device__ unsigned short g_bufHA[(size_t)TSTEPS * NSEQ * 16];
__device__ unsigned short g_bufHB[(size_t)TSTEPS * NSEQ * 16];
__device__ unsigned short g_rawH[(size_t)NSEQ * TSTEPS * 8];

// ---------- raw fp32 -> fp16 convert pre-pass ----------
__global__ void __launch_bounds__(256) cvt_kernel(const float4* __restrict__ in,
                                                  uint2* __restrict__ outp) {
    int i = blockIdx.x * blockDim.x + threadIdx.x;
    float4 v = in[i];
    __half2 h0 = __floats2half2_rn(v.x, v.y);
    __half2 h1 = __floats2half2_rn(v.z, v.w);
    outp[i] = make_uint2(*(unsigned*)&h0, *(unsigned*)&h1);
}

// ---------- per-WARP cp.async x-tile loader ----------
// One 16-row fp16 tile per chunk: row r = (step-in-chunk)*4 + scan, data 2*INF bytes.
template <int INF, bool L0IN>
__device__ __forceinline__ void issue_chunk(unsigned dst_s, const __half* __restrict__ x,
                                            int n0, int c, int dir, int lane) {
    int r, hsel; bool pred;
    if (INF == 16) { r = lane >> 1; hsel = lane & 1; pred = true; }
    else           { r = lane & 15; hsel = 0;        pred = lane < 16; }
    int s = c * CHUNK_T + (r >> 2);
    int scan = r & 3;
    int t = dir ? (TSTEPS - 1 - s) : s;
    const __half* g = L0IN
        ? x + ((size_t)(n0 + scan) * TSTEPS + t) * 8
        : x + ((size_t)t * NSEQ + (n0 + scan)) * 16 + hsel * 8;
    unsigned d = dst_s + r * ROWB + hsel * 16;
    if (pred)
        asm volatile("cp.async.cg.shared.global [%0], [%1], 16;" :: "r"(d), "l"(g));
}

// One bidirectional-GRU layer. Each WARP owns 4 scans of one direction.
// x-projection done on TENSOR CORES: per 4-step batch, ldmatrix loads the
// 16x(K) fp16 x-tile as an A fragment; 3x mma.sync.m16n8k{16,8} (fp16 in,
// FP32 ACCUMULATE, bias in C) produce all 24 gate pre-activations for
// 4 steps x 4 scans; D fragments go through a bank-padded smem buffer to
// reach the recurrence lanes. Only the h-recurrence (12 FFMA2) + gates stay
// on the fp32 pipe. h is fp32 within the layer; inter-layer handoff is fp16.
// HEAD (layer 3): fwd only, no stores; fused 1-step bwd GRU at t=T-1 (h0=0)
// + lin1/LeakyReLU(0.2)/lin2 head (fp32).
template <int INF, bool L0IN, bool HEAD>
__global__ void __launch_bounds__(128, 4)
gru_layer_kernel(const __half* __restrict__ x_in, __half* __restrict__ x_out,
                 const float* __restrict__ Wih, const float* __restrict__ Whh,
                 const float* __restrict__ bih, const float* __restrict__ bhh,
                 int wih_stride,
                 const float* __restrict__ l1w, const float* __restrict__ l1b,
                 const float* __restrict__ l2w, const float* __restrict__ l2b,
                 float* __restrict__ out)
{
    extern __shared__ char sb[];

    const int tid = threadIdx.x;
    const int wid = tid >> 5;
    const int lane = tid & 31;
    const int u = tid & 7;
    const int sg = (tid >> 3) & 3;               // scan within warp
    const int warpG = blockIdx.x * 4 + wid;
    const int dir = HEAD ? 0 : (warpG / (NSEQ / 4));
    const int wi  = HEAD ? warpG : (warpG % (NSEQ / 4));
    const int n0 = wi * 4;
    const int n = n0 + sg;

    char* wsb = sb + wid * WARP_SMEM;            // warp-private region
    char* gsm = wsb + RING * TILE_B;             // gate buffer (fp32)
    const unsigned wsb_s = (unsigned)__cvta_generic_to_shared(wsb);
    float* gw = reinterpret_cast<float*>(gsm);

    const float* wih = Wih + dir * wih_stride;
    const float* whh = Whh + dir * 192;
    const float* bi  = bih + dir * 24;
    const float* bh  = bhh + dir * 24;

    // ---- B fragments (x-projection weights, fp16, pre-scaled) ----
    // B col-major [K, 24]: B[k][m] = scale(m) * Wih[m][k]; 3 n8 tiles.
    const int bg = lane >> 2;                    // n-within-tile
    const int bt = lane & 3;                     // k-pair index
    unsigned bfr[6];
#pragma unroll
    for (int j = 0; j < 3; j++) {
        int m = j * 8 + bg;
        float sc = (m < 16) ? KRZ : 1.0f;
        const float* wrow = wih + m * INF + 2 * bt;
        __half2 h0 = __floats2half2_rn(sc * wrow[0], sc * wrow[1]);
        if (INF == 16) {
            __half2 h1 = __floats2half2_rn(sc * wrow[8], sc * wrow[9]);
            bfr[2 * j]     = *(unsigned*)&h0;
            bfr[2 * j + 1] = *(unsigned*)&h1;
        } else {
            bfr[j] = *(unsigned*)&h0;            // k8 path uses bfr[j]
        }
    }
    // C-fragment biases (per-column): r/z cols get 0.5*(bi+bh); n cols bi only.
    float cb0[3], cb1[3];
#pragma unroll
    for (int j = 0; j < 3; j++) {
        int c0 = j * 8 + 2 * bt;
        cb0[j] = (c0     < 16) ? KRZ * (bi[c0]     + bh[c0])     : bi[c0];
        cb1[j] = (c0 + 1 < 16) ? KRZ * (bi[c0 + 1] + bh[c0 + 1]) : bi[c0 + 1];
    }

    // ---- h-recurrence weights (fp32 packed, pre-scaled) ----
    u64 ur[4], uz[4], un[4];
#pragma unroll
    for (int p = 0; p < 4; p++) {
        ur[p] = pk2(KRZ * whh[(u     ) * 8 + 2 * p], KRZ * whh[(u     ) * 8 + 2 * p + 1]);
        uz[p] = pk2(KRZ * whh[(u +  8) * 8 + 2 * p], KRZ * whh[(u +  8) * 8 + 2 * p + 1]);
        un[p] = pk2(       whh[(u + 16) * 8 + 2 * p],        whh[(u + 16) * 8 + 2 * p + 1]);
    }
    const u64 bnhp = pk2(bh[u + 16], 0.0f);

    const int t0 = dir ? (TSTEPS - 1) : 0;
    __half* op = HEAD ? nullptr
                      : (x_out + ((size_t)t0 * NSEQ + (size_t)n) * 16 + dir * 8 + u);
    const ptrdiff_t ostep = (ptrdiff_t)NSEQ * 16 * (dir ? -1 : 1);

    // ---- prime the x pipeline (3 chunks in flight) ----
    issue_chunk<INF, L0IN>(wsb_s + 0 * TILE_B, x_in, n0, 0, dir, lane);
    asm volatile("cp.async.commit_group;" ::: "memory");
    issue_chunk<INF, L0IN>(wsb_s + 1 * TILE_B, x_in, n0, 1, dir, lane);
    asm volatile("cp.async.commit_group;" ::: "memory");
    issue_chunk<INF, L0IN>(wsb_s + 2 * TILE_B, x_in, n0, 2, dir, lane);
    asm volatile("cp.async.commit_group;" ::: "memory");

    float h = 0.0f;
    const int dg = lane >> 2;                    // D-frag row group
    const int dcol = 2 * (lane & 3);             // D-frag col pair base

#pragma unroll 1
    for (int c = 0; c < NCHUNK; c++) {
        asm volatile("cp.async.wait_group 2;" ::: "memory");
        __syncwarp();
        const unsigned tile_s = wsb_s + (c & (RING - 1)) * TILE_B;

        // ---- MMA phase: x-projection for 4 steps x 4 scans ----
        unsigned a0, a1, a2, a3;
        if (INF == 16) {
            unsigned la = tile_s + (lane & 15) * ROWB + (lane >> 4) * 16;
            asm volatile("ldmatrix.sync.aligned.m8n8.x4.shared.b16 {%0,%1,%2,%3}, [%4];"
                         : "=r"(a0), "=r"(a1), "=r"(a2), "=r"(a3) : "r"(la));
        } else {
            unsigned la = tile_s + (lane & 15) * ROWB;
            asm volatile("ldmatrix.sync.aligned.m8n8.x2.shared.b16 {%0,%1}, [%2];"
                         : "=r"(a0), "=r"(a1) : "r"(la));
        }
#pragma unroll
        for (int j = 0; j < 3; j++) {
            float d0 = cb0[j], d1 = cb1[j], d2 = cb0[j], d3 = cb1[j];
            if (INF == 16)
                asm("mma.sync.aligned.m16n8k16.row.col.f32.f16.f16.f32 "
                    "{%0,%1,%2,%3}, {%4,%5,%6,%7}, {%8,%9}, {%0,%1,%2,%3};"
                    : "+f"(d0), "+f"(d1), "+f"(d2), "+f"(d3)
                    : "r"(a0), "r"(a1), "r"(a2), "r"(a3),
                      "r"(bfr[2 * j]), "r"(bfr[2 * j + 1]));
            else
                asm("mma.sync.aligned.m16n8k8.row.col.f32.f16.f16.f32 "
                    "{%0,%1,%2,%3}, {%4,%5}, {%6}, {%0,%1,%2,%3};"
                    : "+f"(d0), "+f"(d1), "+f"(d2), "+f"(d3)
                    : "r"(a0), "r"(a1), "r"(bfr[j]));
            int col = j * 8 + dcol;
            *(float2*)(gw + dg * GRS + col)       = make_float2(d0, d1);
            *(float2*)(gw + (dg + 8) * GRS + col) = make_float2(d2, d3);
        }
        __syncwarp();

        // ---- recurrence: 4 steps ----
#pragma unroll
        for (int tt = 0; tt < CHUNK_T; tt++) {
            const int grow = (tt * 4 + sg) * GRS;
            float gr = gw[grow + u];             // 0.5*(Wr x + br_i + br_h)
            float gz = gw[grow + 8 + u];
            float gn = gw[grow + 16 + u];        // Wn x + bn_i

            u64 hp[4];
#pragma unroll
            for (int p = 0; p < 4; p++) {
                float lo = __shfl_sync(0xffffffffu, h, 2 * p,     8);
                float hi = __shfl_sync(0xffffffffu, h, 2 * p + 1, 8);
                hp[p] = pk2(lo, hi);
            }
            u64 ar = 0ULL, az = 0ULL, ahn = bnhp;
#pragma unroll
            for (int p = 0; p < 4; p++) {
                ar  = ffma2(ur[p], hp[p], ar);
                az  = ffma2(uz[p], hp[p], az);
                ahn = ffma2(un[p], hp[p], ahn);
            }
            float sr = gr + hsum(ar);
            float sz = gz + hsum(az);
            float shn = hsum(ahn);
            float r = fmaf(0.5f, tanh_a(sr), 0.5f);   // sigmoid
            float z = fmaf(0.5f, tanh_a(sz), 0.5f);   // sigmoid
            float nn = tanh_a(fmaf(r, shn, gn));
            h = fmaf(z, h - nn, nn);

            if (!HEAD) { *op = __float2half_rn(h); op += ostep; }
        }

        if (c + 3 < NCHUNK)
            issue_chunk<INF, L0IN>(wsb_s + ((c + 3) & (RING - 1)) * TILE_B,
                                   x_in, n0, c + 3, dir, lane);
        asm volatile("cp.async.commit_group;" ::: "memory");
    }

    if (HEAD) {
        // x[T-1] fp16 still resident: last chunk's tile, row 12+sg.
        const __half2* xh = (const __half2*)(wsb + ((NCHUNK - 1) & (RING - 1)) * TILE_B
                                             + (12 + sg) * ROWB);
        u64 xcp[8];
#pragma unroll
        for (int p = 0; p < 8; p++) {
            float2 f = __half22float2(xh[p]);
            xcp[p] = pk2(f.x, f.y);
        }
        // backward-direction single step at t=T-1, h0=0 (gh = b_hh); fp32.
        const float* wihB = Wih + wih_stride;
        const float* biB  = bih + 24;
        const float* bhB  = bhh + 24;
        u64 br2 = pk2(KRZ * (biB[u]     + bhB[u]),     0.0f);
        u64 bz2 = pk2(KRZ * (biB[u + 8] + bhB[u + 8]), 0.0f);
        u64 bx2 = pk2(biB[u + 16], 0.0f);
        const float bnhB = bhB[u + 16];
#pragma unroll
        for (int p = 0; p < 8; p++) {
            u64 wrB = pk2(KRZ * wihB[(u     ) * 16 + 2 * p], KRZ * wihB[(u     ) * 16 + 2 * p + 1]);
            u64 wzB = pk2(KRZ * wihB[(u +  8) * 16 + 2 * p], KRZ * wihB[(u +  8) * 16 + 2 * p + 1]);
            u64 wnB = pk2(       wihB[(u + 16) * 16 + 2 * p],        wihB[(u + 16) * 16 + 2 * p + 1]);
            br2 = ffma2(wrB, xcp[p], br2);
            bz2 = ffma2(wzB, xcp[p], bz2);
            bx2 = ffma2(wnB, xcp[p], bx2);
        }
        float r = fmaf(0.5f, tanh_a(hsum(br2)), 0.5f);
        float z = fmaf(0.5f, tanh_a(hsum(bz2)), 0.5f);
        float nn = tanh_a(fmaf(r, bnhB, hsum(bx2)));
        float hb = (1.0f - z) * nn;   // h0 = 0

        // head: lin1 + LeakyReLU(0.2) + lin2 over [h_f ; h_b]
        float mid = l1b[u];
#pragma unroll
        for (int cc = 0; cc < 8; cc++) {
            float hf_c = __shfl_sync(0xffffffffu, h,  cc, 8);
            float hb_c = __shfl_sync(0xffffffffu, hb, cc, 8);
            mid = fmaf(l1w[u * 16 + cc],     hf_c, mid);
            mid = fmaf(l1w[u * 16 + 8 + cc], hb_c, mid);
        }
        float act = (mid >= 0.0f) ? mid : 0.2f * mid;

        float o = l2b[u];
#pragma unroll
        for (int cc = 0; cc < 8; cc++) {
            float a_c = __shfl_sync(0xffffffffu, act, cc, 8);
            o = fmaf(l2w[u * 8 + cc], a_c, o);
        }
        out[(size_t)n * 8 + u] = o;
    }
}

extern "C" void kernel_launch(void* const* d_in, const int* in_sizes, int n_in,
                              void* d_out, int out_size) {
    (void)in_sizes; (void)n_in; (void)out_size;
    const float* raw  = (const float*)d_in[0];
    const float* Wih0 = (const float*)d_in[1];
    const float* Whh0 = (const float*)d_in[2];
    const float* bih0 = (const float*)d_in[3];
    const float* bhh0 = (const float*)d_in[4];
    const float* WihR = (const float*)d_in[5];   // (3, 2, 24, 16)
    const float* WhhR = (const float*)d_in[6];   // (3, 2, 24, 8)
    const float* bihR = (const float*)d_in[7];   // (3, 2, 24)
    const float* bhhR = (const float*)d_in[8];   // (3, 2, 24)
    const float* l1w  = (const float*)d_in[9];
    const float* l1b  = (const float*)d_in[10];
    const float* l2w  = (const float*)d_in[11];
    const float* l2b  = (const float*)d_in[12];
    float* out = (float*)d_out;

    __half *bufA, *bufB, *rawH;
    cudaGetSymbolAddress((void**)&bufA, g_bufHA);
    cudaGetSymbolAddress((void**)&bufB, g_bufHB);
    cudaGetSymbolAddress((void**)&rawH, g_rawH);

    const int BLK_FULL = 2 * (NSEQ / 16);   // 1600 blocks (fwd + bwd)
    const int BLK_HEAD = NSEQ / 16;         // 800 blocks (fwd only)
    const int SMEM = 4 * WARP_SMEM;         // 18944 B

    // Pre-pass: raw fp32 -> fp16 (N, T, 8)
    cvt_kernel<<<(NSEQ * TSTEPS * 8) / (256 * 4), 256>>>(
        (const float4*)raw, (uint2*)rawH);

    // Layer 0: rawH -> bufA  (K=8 MMA)
    gru_layer_kernel<8, true, false><<<BLK_FULL, 128, SMEM>>>(
        rawH, bufA, Wih0, Whh0, bih0, bhh0, 192,
        nullptr, nullptr, nullptr, nullptr, nullptr);

    // Layer 1: bufA -> bufB
    gru_layer_kernel<16, false, false><<<BLK_FULL, 128, SMEM>>>(
        bufA, bufB, WihR + 0 * 768, WhhR + 0 * 384, bihR + 0 * 48, bhhR + 0 * 48, 384,
        nullptr, nullptr, nullptr, nullptr, nullptr);

    // Layer 2: bufB -> bufA
    gru_layer_kernel<16, false, false><<<BLK_FULL, 128, SMEM>>>(
        bufB, bufA, WihR + 1 * 768, WhhR + 1 * 384, bihR + 1 * 48, bhhR + 1 * 48, 384,
        nullptr, nullptr, nullptr, nullptr, nullptr);

    // Layer 3 + head: bufA -> out
    gru_layer_kernel<16, false, true><<<BLK_HEAD, 128, SMEM>>>(
        bufA, nullptr, WihR + 2 * 768, WhhR + 2 * 384, bihR + 2 * 48, bhhR + 2 * 48, 384,
        l1w, l1b, l2w, l2b, out);
}